// round 8
// baseline (speedup 1.0000x reference)
#include <cuda_runtime.h>

// SpectralConv2d via truncated-mode DFTs, fp32 SIMT, register-tiled.

#define BB 16
#define CC 64
#define HH 256
#define WW 256
#define M1 20
#define M2 20
#define QQ 40   // q<20 -> ky=236+q (w2, m=q); q>=20 -> ky=q-20 (w1, m=q-20); freq f = q-20

__device__ float2 g_Y1[BB*CC*HH*M2];   // after W-DFT   [b,c,h,k2]
__device__ float2 g_Zq[BB*CC*QQ*M2];   // after H-DFT   [b,c,q,k2]
__device__ float2 g_Zo[BB*CC*QQ*M2];   // after mixing  [b,o,q,k2]

// ---------------------------------------------------------------------------
// Stage A: Y1[row,k] = sum_w x[row,w] e^{-2pi i k w/256}, k=0..19.
// Folded real input. Block: 256 rows, 256 threads; thread -> (4 rows, 5 k).
// ---------------------------------------------------------------------------
#define RA 256
#define WCH 32
__global__ void __launch_bounds__(256, 2) kA(const float* __restrict__ x) {
    __shared__ float2 tw[256];
    __shared__ float2 sf[RA][WCH + 1];   // 67.6KB: (u,v); chunk0 [..][0] = (x0,x128)
    __shared__ float2 twa[WCH][M2];      // 5KB
    int tid = threadIdx.x;
    {
        float s, c;
        sincospif((float)tid * (1.0f / 128.0f), &s, &c);
        tw[tid] = make_float2(c, s);
    }
    int row0 = blockIdx.x * RA;
    int rg = tid >> 2;             // 0..63 -> rows 4rg..4rg+3
    int k0 = (tid & 3) * 5;

    float ar[4][5], ai[4][5];
    #pragma unroll
    for (int u = 0; u < 4; ++u)
        #pragma unroll
        for (int j = 0; j < 5; ++j) { ar[u][j] = 0.0f; ai[u][j] = 0.0f; }
    float2 e[4];
    #pragma unroll
    for (int u = 0; u < 4; ++u) e[u] = make_float2(0.f, 0.f);

    for (int wc = 0; wc < 128; wc += WCH) {
        __syncthreads();
        for (int t = tid; t < RA * WCH; t += 256) {
            int r = t >> 5, wl = t & 31;
            int w = wc + wl;
            const float* xr = x + (size_t)(row0 + r) * WW;
            float a = xr[w];
            if (w == 0) {
                sf[r][wl] = make_float2(a, xr[128]);
            } else {
                float b = xr[256 - w];
                sf[r][wl] = make_float2(a + b, a - b);
            }
        }
        for (int t = tid; t < WCH * M2; t += 256) {
            int wl = t / M2, k = t - wl * M2;
            twa[wl][k] = tw[((wc + wl) * k) & 255];
        }
        __syncthreads();

        int wl0 = 0;
        if (wc == 0) {
            #pragma unroll
            for (int u = 0; u < 4; ++u) e[u] = sf[4 * rg + u][0];
            wl0 = 1;
        }

        #pragma unroll 2
        for (int wl = wl0; wl < WCH; ++wl) {
            float2 uv[4];
            #pragma unroll
            for (int u = 0; u < 4; ++u) uv[u] = sf[4 * rg + u][wl];
            #pragma unroll
            for (int j = 0; j < 5; ++j) {
                float2 cs = twa[wl][k0 + j];
                #pragma unroll
                for (int u = 0; u < 4; ++u) {
                    ar[u][j] = fmaf(uv[u].x, cs.x, ar[u][j]);
                    ai[u][j] = fmaf(uv[u].y, cs.y, ai[u][j]);
                }
            }
        }
    }

    #pragma unroll
    for (int u = 0; u < 4; ++u) {
        float2* yo = g_Y1 + (size_t)(row0 + 4 * rg + u) * M2;
        #pragma unroll
        for (int j = 0; j < 5; ++j) {
            int k = k0 + j;
            float re = ar[u][j] + e[u].x + ((k & 1) ? -e[u].y : e[u].y);
            yo[k] = make_float2(re, -ai[u][j]);
        }
    }
}

// ---------------------------------------------------------------------------
// Stage B: Zq[bc,q,k2] = sum_h Y1[bc,h,k2] e^{-2pi i f h/256}, f=q-20.
// h<->h+128 parity fold. Block per bc; thread -> (q, 4 k2), LDS.128 Y loads.
// ---------------------------------------------------------------------------
__global__ void __launch_bounds__(256) kB() {
    __shared__ float2 tw[256];
    __shared__ float2 sYp[128][M2];  // 20KB
    __shared__ float2 sYm[128][M2];  // 20KB
    int tid = threadIdx.x;
    {
        float s, c;
        sincospif((float)tid * (1.0f / 128.0f), &s, &c);
        tw[tid] = make_float2(c, s);
    }
    int bc = blockIdx.x;
    const float2* ysrc = g_Y1 + (size_t)bc * HH * M2;
    for (int t = tid; t < 128 * M2; t += 256) {
        int h = t / M2, k = t - h * M2;
        float2 a = ysrc[t];
        float2 b = ysrc[t + 128 * M2];
        sYp[h][k] = make_float2(a.x + b.x, a.y + b.y);
        sYm[h][k] = make_float2(a.x - b.x, a.y - b.y);
    }
    __syncthreads();

    if (tid < 200) {
        int q = tid / 5;
        int k0 = (tid % 5) * 4;
        int f = q - M1;
        const float2 (*Ys)[M2] = (f & 1) ? sYm : sYp;
        float ar[4] = {0, 0, 0, 0}, ai[4] = {0, 0, 0, 0};
        int idx = 0, step = f & 255;
        #pragma unroll 4
        for (int h = 0; h < 128; ++h) {
            float2 cs = tw[idx];
            float4 yab = *(const float4*)&Ys[h][k0];
            float4 ycd = *(const float4*)&Ys[h][k0 + 2];
            float yx[4] = {yab.x, yab.z, ycd.x, ycd.z};
            float yy[4] = {yab.y, yab.w, ycd.y, ycd.w};
            #pragma unroll
            for (int j = 0; j < 4; ++j) {
                ar[j] = fmaf(yx[j], cs.x, fmaf(yy[j], cs.y, ar[j]));
                ai[j] = fmaf(yy[j], cs.x, fmaf(-yx[j], cs.y, ai[j]));
            }
            idx = (idx + step) & 255;
        }
        float2* zo = g_Zq + (size_t)bc * QQ * M2 + q * M2 + k0;
        #pragma unroll
        for (int j = 0; j < 4; ++j) zo[j] = make_float2(ar[j], ai[j]);
    }
}

// ---------------------------------------------------------------------------
// Stage C: Zo[b,o,q,k2] = sum_i Zq[b,i,q,k2] * Wsel[i,o,m,k2]  (complex)
// Block per (q, k2-quad); weights loaded as float4 across 4 k2 (LDG.128);
// thread -> (o, 4 b, 4 k2).
// ---------------------------------------------------------------------------
__global__ void __launch_bounds__(256) kC(const float* __restrict__ w1r, const float* __restrict__ w1i,
                                          const float* __restrict__ w2r, const float* __restrict__ w2i) {
    __shared__ float2 sZ[BB][CC][4];  // 32KB
    int tid = threadIdx.x;
    int q = blockIdx.x / 5, k2b = (blockIdx.x % 5) * 4;

    for (int t = tid; t < BB * CC * 2; t += 256) {
        int pair = t & 1;
        int ci = t >> 1;                 // b*64 + i
        float4 v = *(const float4*)&g_Zq[(size_t)ci * (QQ * M2) + q * M2 + k2b + pair * 2];
        *(float4*)&sZ[ci >> 6][ci & 63][pair * 2] = v;
    }

    const float *wr, *wi;
    int m;
    if (q < M1) { wr = w2r; wi = w2i; m = q; }
    else        { wr = w1r; wi = w1i; m = q - M1; }
    __syncthreads();

    int o = tid & 63;
    int bq = tid >> 6;   // b = bq + 4j
    float ar[4][4], ai[4][4];
    #pragma unroll
    for (int j = 0; j < 4; ++j)
        #pragma unroll
        for (int kk = 0; kk < 4; ++kk) { ar[j][kk] = 0.f; ai[j][kk] = 0.f; }

    size_t wbase = (size_t)o * (M1 * M2) + m * M2 + k2b;
    #pragma unroll 2
    for (int i = 0; i < CC; ++i) {
        float4 wr4 = *(const float4*)&wr[wbase + (size_t)i * (CC * M1 * M2)];
        float4 wi4 = *(const float4*)&wi[wbase + (size_t)i * (CC * M1 * M2)];
        float wra[4] = {wr4.x, wr4.y, wr4.z, wr4.w};
        float wia[4] = {wi4.x, wi4.y, wi4.z, wi4.w};
        #pragma unroll
        for (int j = 0; j < 4; ++j) {
            float4 za = *(const float4*)&sZ[bq + 4 * j][i][0];
            float4 zb = *(const float4*)&sZ[bq + 4 * j][i][2];
            float zx[4] = {za.x, za.z, zb.x, zb.z};
            float zy[4] = {za.y, za.w, zb.y, zb.w};
            #pragma unroll
            for (int kk = 0; kk < 4; ++kk) {
                ar[j][kk] = fmaf(zx[kk], wra[kk], fmaf(-zy[kk], wia[kk], ar[j][kk]));
                ai[j][kk] = fmaf(zx[kk], wia[kk], fmaf( zy[kk], wra[kk], ai[j][kk]));
            }
        }
    }
    #pragma unroll
    for (int j = 0; j < 4; ++j) {
        int b = bq + 4 * j;
        float2* zo = g_Zo + (((size_t)(b * CC + o)) * QQ + q) * M2 + k2b;
        float4 v0 = make_float4(ar[j][0], ai[j][0], ar[j][1], ai[j][1]);
        float4 v1 = make_float4(ar[j][2], ai[j][2], ar[j][3], ai[j][3]);
        *(float4*)&zo[0] = v0;
        *(float4*)&zo[2] = v1;
    }
}

// ---------------------------------------------------------------------------
// Stage D (fused): block = one bo (grid 1024), 2 CTAs/SM.
// phase1: G[h,k] = sum_q Zo[q,k] e^{+2pi i (q-20)h/256}, h<->h+128 fold via
//         q-parity; two passes of 5 k to bound registers. Transposed store.
// phase2: 4h x 4w register tile; twiddles from smem tables.
// ---------------------------------------------------------------------------
__global__ void __launch_bounds__(256, 2) kD(float* __restrict__ out) {
    __shared__ float2 tw[256];          // 2KB
    __shared__ float2 sZ[QQ][M2];       // 6.25KB
    __shared__ float  sGx[M2][HH];      // 20KB
    __shared__ float  sGy[M2 - 1][HH];  // 19KB
    __shared__ float  sC[M2][128];      // 10KB
    __shared__ float  sS[M2][128];      // 10KB
    int tid = threadIdx.x;
    {
        float s, c;
        sincospif((float)tid * (1.0f / 128.0f), &s, &c);
        tw[tid] = make_float2(c, s);
    }
    int bo = blockIdx.x;

    const float4* zsrc = (const float4*)(g_Zo + (size_t)bo * QQ * M2);
    float4* zdst = (float4*)&sZ[0][0];
    for (int t = tid; t < QQ * M2 / 2; t += 256) zdst[t] = zsrc[t];
    __syncthreads();

    for (int t = tid; t < M2 * 128; t += 256) {
        int k = t >> 7, wp = t & 127;
        float2 cs = tw[(k * wp) & 255];
        sC[k][wp] = cs.x;
        sS[k][wp] = cs.y;
    }

    // ---- phase 1: two passes of 5 k ----
    {
        int h = tid & 127;
        int khalf = (tid >> 7) * 10;
        int step = (2 * h) & 255;
        #pragma unroll 1
        for (int ks = 0; ks < 2; ++ks) {
            int k0 = khalf + ks * 5;
            float ger[5], gei[5], gor[5], goi[5];
            #pragma unroll
            for (int j = 0; j < 5; ++j) { ger[j] = gei[j] = gor[j] = goi[j] = 0.f; }

            int idx = (-20 * h) & 255;
            #pragma unroll 4
            for (int qq = 0; qq < 20; ++qq) {
                float2 cs = tw[idx];
                #pragma unroll
                for (int j = 0; j < 5; ++j) {
                    float2 Z = sZ[2 * qq][k0 + j];
                    ger[j] = fmaf(Z.x, cs.x, fmaf(-Z.y, cs.y, ger[j]));
                    gei[j] = fmaf(Z.x, cs.y, fmaf( Z.y, cs.x, gei[j]));
                }
                idx = (idx + step) & 255;
            }
            idx = (-19 * h) & 255;
            #pragma unroll 4
            for (int qq = 0; qq < 20; ++qq) {
                float2 cs = tw[idx];
                #pragma unroll
                for (int j = 0; j < 5; ++j) {
                    float2 Z = sZ[2 * qq + 1][k0 + j];
                    gor[j] = fmaf(Z.x, cs.x, fmaf(-Z.y, cs.y, gor[j]));
                    goi[j] = fmaf(Z.x, cs.y, fmaf( Z.y, cs.x, goi[j]));
                }
                idx = (idx + step) & 255;
            }
            #pragma unroll
            for (int j = 0; j < 5; ++j) {
                int k = k0 + j;
                sGx[k][h]       = ger[j] + gor[j];
                sGx[k][h + 128] = ger[j] - gor[j];
                if (k > 0) {
                    sGy[k - 1][h]       = gei[j] + goi[j];
                    sGy[k - 1][h + 128] = gei[j] - goi[j];
                }
            }
        }
    }
    __syncthreads();

    // ---- phase 2 ----
    int wg = tid & 31;
    int hgb = tid >> 5;
    int wp0 = wg * 4;
    const float sc = 2.0f / 65536.0f;

    #pragma unroll 1
    for (int it = 0; it < 8; ++it) {
        int h0 = it * 32 + hgb * 4;
        float C[4][4], S[4][4];
        {
            float4 g0 = *(const float4*)&sGx[0][h0];
            float g0a[4] = {g0.x, g0.y, g0.z, g0.w};
            #pragma unroll
            for (int a = 0; a < 4; ++a)
                #pragma unroll
                for (int b = 0; b < 4; ++b) { C[a][b] = 0.5f * g0a[a]; S[a][b] = 0.f; }
        }
        #pragma unroll
        for (int k = 1; k < M2; ++k) {
            float4 gx = *(const float4*)&sGx[k][h0];
            float4 gy = *(const float4*)&sGy[k - 1][h0];
            float4 cv = *(const float4*)&sC[k][wp0];
            float4 sv = *(const float4*)&sS[k][wp0];
            float gxa[4] = {gx.x, gx.y, gx.z, gx.w};
            float gya[4] = {gy.x, gy.y, gy.z, gy.w};
            float cva[4] = {cv.x, cv.y, cv.z, cv.w};
            float sva[4] = {sv.x, sv.y, sv.z, sv.w};
            #pragma unroll
            for (int a = 0; a < 4; ++a)
                #pragma unroll
                for (int b = 0; b < 4; ++b) {
                    C[a][b] = fmaf(gxa[a], cva[b], C[a][b]);
                    S[a][b] = fmaf(gya[a], sva[b], S[a][b]);
                }
        }

        size_t rowbase = ((size_t)bo * HH + h0) * WW;
        #pragma unroll
        for (int a = 0; a < 4; ++a) {
            float4 fo;
            fo.x = (C[a][0] - S[a][0]) * sc;
            fo.y = (C[a][1] - S[a][1]) * sc;
            fo.z = (C[a][2] - S[a][2]) * sc;
            fo.w = (C[a][3] - S[a][3]) * sc;
            *(float4*)&out[rowbase + (size_t)a * WW + wp0] = fo;
            #pragma unroll
            for (int b = 0; b < 4; ++b) {
                int wp = wp0 + b;
                if (wp) out[rowbase + (size_t)a * WW + (256 - wp)] = (C[a][b] + S[a][b]) * sc;
            }
        }
    }

    // ---- w = 128 column ----
    {
        int h = tid;
        float acc = 0.5f * sGx[0][h];
        #pragma unroll
        for (int k = 1; k < M2; ++k)
            acc += (k & 1) ? -sGx[k][h] : sGx[k][h];
        out[((size_t)bo * HH + h) * WW + 128] = acc * sc;
    }
}

extern "C" void kernel_launch(void* const* d_in, const int* in_sizes, int n_in,
                              void* d_out, int out_size) {
    const float* x   = (const float*)d_in[0];
    const float* w1r = (const float*)d_in[1];
    const float* w1i = (const float*)d_in[2];
    const float* w2r = (const float*)d_in[3];
    const float* w2i = (const float*)d_in[4];
    float* out = (float*)d_out;

    kA<<<(BB * CC * HH) / RA, 256>>>(x);       // 1024 blocks
    kB<<<BB * CC, 256>>>();                     // 1024 blocks
    kC<<<QQ * 5, 256>>>(w1r, w1i, w2r, w2i);    // 200 blocks
    kD<<<BB * CC, 256>>>(out);                  // 1024 blocks
}

// round 9
// speedup vs baseline: 1.2402x; 1.2402x over previous
#include <cuda_runtime.h>

// SpectralConv2d via truncated-mode DFTs, fp32 SIMT, register-tiled.

#define BB 16
#define CC 64
#define HH 256
#define WW 256
#define M1 20
#define M2 20
#define QQ 40   // q<20 -> ky=236+q (w2, m=q); q>=20 -> ky=q-20 (w1, m=q-20); freq f = q-20

__device__ float2 g_Y1[BB*CC*HH*M2];   // after W-DFT   [b,c,h,k2]
__device__ float2 g_Zq[BB*CC*QQ*M2];   // after H-DFT   [b,c,q,k2]
__device__ float2 g_Zo[BB*CC*QQ*M2];   // after mixing  [b,o,q,k2]

// ---------------------------------------------------------------------------
// Stage A: Y1[row,k] = sum_w x[row,w] e^{-2pi i k w/256}, k=0..19.
// Folded real input. Block: 256 rows, 256 threads; thread -> (4 rows, 5 k).
// ---------------------------------------------------------------------------
#define RA 256
#define WCH 32
__global__ void __launch_bounds__(256, 2) kA(const float* __restrict__ x) {
    __shared__ float2 tw[256];
    __shared__ float2 sf[RA][WCH + 1];   // 67.6KB: (u,v); chunk0 [..][0] = (x0,x128)
    __shared__ float2 twa[WCH][M2];      // 5KB
    int tid = threadIdx.x;
    {
        float s, c;
        sincospif((float)tid * (1.0f / 128.0f), &s, &c);
        tw[tid] = make_float2(c, s);
    }
    int row0 = blockIdx.x * RA;
    int rg = tid >> 2;             // 0..63 -> rows 4rg..4rg+3
    int k0 = (tid & 3) * 5;

    float ar[4][5], ai[4][5];
    #pragma unroll
    for (int u = 0; u < 4; ++u)
        #pragma unroll
        for (int j = 0; j < 5; ++j) { ar[u][j] = 0.0f; ai[u][j] = 0.0f; }
    float2 e[4];
    #pragma unroll
    for (int u = 0; u < 4; ++u) e[u] = make_float2(0.f, 0.f);

    for (int wc = 0; wc < 128; wc += WCH) {
        __syncthreads();
        for (int t = tid; t < RA * WCH; t += 256) {
            int r = t >> 5, wl = t & 31;
            int w = wc + wl;
            const float* xr = x + (size_t)(row0 + r) * WW;
            float a = xr[w];
            if (w == 0) {
                sf[r][wl] = make_float2(a, xr[128]);
            } else {
                float b = xr[256 - w];
                sf[r][wl] = make_float2(a + b, a - b);
            }
        }
        for (int t = tid; t < WCH * M2; t += 256) {
            int wl = t / M2, k = t - wl * M2;
            twa[wl][k] = tw[((wc + wl) * k) & 255];
        }
        __syncthreads();

        int wl0 = 0;
        if (wc == 0) {
            #pragma unroll
            for (int u = 0; u < 4; ++u) e[u] = sf[4 * rg + u][0];
            wl0 = 1;
        }

        #pragma unroll 2
        for (int wl = wl0; wl < WCH; ++wl) {
            float2 uv[4];
            #pragma unroll
            for (int u = 0; u < 4; ++u) uv[u] = sf[4 * rg + u][wl];
            #pragma unroll
            for (int j = 0; j < 5; ++j) {
                float2 cs = twa[wl][k0 + j];
                #pragma unroll
                for (int u = 0; u < 4; ++u) {
                    ar[u][j] = fmaf(uv[u].x, cs.x, ar[u][j]);
                    ai[u][j] = fmaf(uv[u].y, cs.y, ai[u][j]);
                }
            }
        }
    }

    #pragma unroll
    for (int u = 0; u < 4; ++u) {
        float2* yo = g_Y1 + (size_t)(row0 + 4 * rg + u) * M2;
        #pragma unroll
        for (int j = 0; j < 5; ++j) {
            int k = k0 + j;
            float re = ar[u][j] + e[u].x + ((k & 1) ? -e[u].y : e[u].y);
            yo[k] = make_float2(re, -ai[u][j]);
        }
    }
}

// ---------------------------------------------------------------------------
// Stage B: Zq[bc,q,k2] = sum_h Y1[bc,h,k2] e^{-2pi i f h/256}, f=q-20.
// h<->h+128 parity fold. Block per bc; thread -> (q, 4 k2), LDS.128 Y loads.
// ---------------------------------------------------------------------------
__global__ void __launch_bounds__(256) kB() {
    __shared__ float2 tw[256];
    __shared__ float2 sYp[128][M2];  // 20KB
    __shared__ float2 sYm[128][M2];  // 20KB
    int tid = threadIdx.x;
    {
        float s, c;
        sincospif((float)tid * (1.0f / 128.0f), &s, &c);
        tw[tid] = make_float2(c, s);
    }
    int bc = blockIdx.x;
    const float2* ysrc = g_Y1 + (size_t)bc * HH * M2;
    for (int t = tid; t < 128 * M2; t += 256) {
        int h = t / M2, k = t - h * M2;
        float2 a = ysrc[t];
        float2 b = ysrc[t + 128 * M2];
        sYp[h][k] = make_float2(a.x + b.x, a.y + b.y);
        sYm[h][k] = make_float2(a.x - b.x, a.y - b.y);
    }
    __syncthreads();

    if (tid < 200) {
        int q = tid / 5;
        int k0 = (tid % 5) * 4;
        int f = q - M1;
        const float2 (*Ys)[M2] = (f & 1) ? sYm : sYp;
        float ar[4] = {0, 0, 0, 0}, ai[4] = {0, 0, 0, 0};
        int idx = 0, step = f & 255;
        #pragma unroll 4
        for (int h = 0; h < 128; ++h) {
            float2 cs = tw[idx];
            float4 yab = *(const float4*)&Ys[h][k0];
            float4 ycd = *(const float4*)&Ys[h][k0 + 2];
            float yx[4] = {yab.x, yab.z, ycd.x, ycd.z};
            float yy[4] = {yab.y, yab.w, ycd.y, ycd.w};
            #pragma unroll
            for (int j = 0; j < 4; ++j) {
                ar[j] = fmaf(yx[j], cs.x, fmaf(yy[j], cs.y, ar[j]));
                ai[j] = fmaf(yy[j], cs.x, fmaf(-yx[j], cs.y, ai[j]));
            }
            idx = (idx + step) & 255;
        }
        float2* zo = g_Zq + (size_t)bc * QQ * M2 + q * M2 + k0;
        #pragma unroll
        for (int j = 0; j < 4; ++j) zo[j] = make_float2(ar[j], ai[j]);
    }
}

// ---------------------------------------------------------------------------
// Stage C: Zo[b,o,q,k2] = sum_i Zq[b,i,q,k2] * Wsel[i,o,m,k2]  (complex)
// Block per (q, k2-quad); weights loaded as float4 across 4 k2 (LDG.128);
// thread -> (o, 4 b, 4 k2).
// ---------------------------------------------------------------------------
__global__ void __launch_bounds__(256) kC(const float* __restrict__ w1r, const float* __restrict__ w1i,
                                          const float* __restrict__ w2r, const float* __restrict__ w2i) {
    __shared__ float2 sZ[BB][CC][4];  // 32KB
    int tid = threadIdx.x;
    int q = blockIdx.x / 5, k2b = (blockIdx.x % 5) * 4;

    for (int t = tid; t < BB * CC * 2; t += 256) {
        int pair = t & 1;
        int ci = t >> 1;                 // b*64 + i
        float4 v = *(const float4*)&g_Zq[(size_t)ci * (QQ * M2) + q * M2 + k2b + pair * 2];
        *(float4*)&sZ[ci >> 6][ci & 63][pair * 2] = v;
    }

    const float *wr, *wi;
    int m;
    if (q < M1) { wr = w2r; wi = w2i; m = q; }
    else        { wr = w1r; wi = w1i; m = q - M1; }
    __syncthreads();

    int o = tid & 63;
    int bq = tid >> 6;   // b = bq + 4j
    float ar[4][4], ai[4][4];
    #pragma unroll
    for (int j = 0; j < 4; ++j)
        #pragma unroll
        for (int kk = 0; kk < 4; ++kk) { ar[j][kk] = 0.f; ai[j][kk] = 0.f; }

    size_t wbase = (size_t)o * (M1 * M2) + m * M2 + k2b;
    #pragma unroll 2
    for (int i = 0; i < CC; ++i) {
        float4 wr4 = *(const float4*)&wr[wbase + (size_t)i * (CC * M1 * M2)];
        float4 wi4 = *(const float4*)&wi[wbase + (size_t)i * (CC * M1 * M2)];
        float wra[4] = {wr4.x, wr4.y, wr4.z, wr4.w};
        float wia[4] = {wi4.x, wi4.y, wi4.z, wi4.w};
        #pragma unroll
        for (int j = 0; j < 4; ++j) {
            float4 za = *(const float4*)&sZ[bq + 4 * j][i][0];
            float4 zb = *(const float4*)&sZ[bq + 4 * j][i][2];
            float zx[4] = {za.x, za.z, zb.x, zb.z};
            float zy[4] = {za.y, za.w, zb.y, zb.w};
            #pragma unroll
            for (int kk = 0; kk < 4; ++kk) {
                ar[j][kk] = fmaf(zx[kk], wra[kk], fmaf(-zy[kk], wia[kk], ar[j][kk]));
                ai[j][kk] = fmaf(zx[kk], wia[kk], fmaf( zy[kk], wra[kk], ai[j][kk]));
            }
        }
    }
    #pragma unroll
    for (int j = 0; j < 4; ++j) {
        int b = bq + 4 * j;
        float2* zo = g_Zo + (((size_t)(b * CC + o)) * QQ + q) * M2 + k2b;
        float4 v0 = make_float4(ar[j][0], ai[j][0], ar[j][1], ai[j][1]);
        float4 v1 = make_float4(ar[j][2], ai[j][2], ar[j][3], ai[j][3]);
        *(float4*)&zo[0] = v0;
        *(float4*)&zo[2] = v1;
    }
}

// ---------------------------------------------------------------------------
// Stage D (fused): block = one bo (grid 1024). UNCAPPED registers (Round-5
// proven config: ~223 regs, 1 CTA/SM, no spills).
// phase1: G[h,k] = sum_q Zo[q,k] e^{+2pi i (q-20)h/256}, folded h<->h+128 via
//         even/odd-q partial sums. Stored transposed: sGx[k][h], sGy[k-1][h].
// phase2: 4h x 4w register tile; twiddles from smem tables sC/sS.
// ---------------------------------------------------------------------------
__global__ void __launch_bounds__(256) kD(float* __restrict__ out) {
    __shared__ float2 tw[256];          // 2KB
    __shared__ float2 sZ[QQ][M2];       // 6.25KB
    __shared__ float  sGx[M2][HH];      // 20KB
    __shared__ float  sGy[M2 - 1][HH];  // 19KB
    __shared__ float  sC[M2][128];      // 10KB
    __shared__ float  sS[M2][128];      // 10KB
    int tid = threadIdx.x;
    {
        float s, c;
        sincospif((float)tid * (1.0f / 128.0f), &s, &c);
        tw[tid] = make_float2(c, s);
    }
    int bo = blockIdx.x;

    const float4* zsrc = (const float4*)(g_Zo + (size_t)bo * QQ * M2);
    float4* zdst = (float4*)&sZ[0][0];
    for (int t = tid; t < QQ * M2 / 2; t += 256) zdst[t] = zsrc[t];
    __syncthreads();

    // ---- twiddle tables for phase 2 ----
    for (int t = tid; t < M2 * 128; t += 256) {
        int k = t >> 7, wp = t & 127;
        float2 cs = tw[(k * wp) & 255];
        sC[k][wp] = cs.x;
        sS[k][wp] = cs.y;
    }

    // ---- phase 1 ----
    {
        int h = tid & 127;
        int k0 = (tid >> 7) * 10;     // 0 or 10
        float ger[10], gei[10], gor[10], goi[10];
        #pragma unroll
        for (int j = 0; j < 10; ++j) { ger[j] = gei[j] = gor[j] = goi[j] = 0.f; }

        int step = (2 * h) & 255;
        // even q (f even), f = -20, -18, ..., 18
        int idx = (-20 * h) & 255;
        #pragma unroll 2
        for (int qq = 0; qq < 20; ++qq) {
            float2 cs = tw[idx];
            #pragma unroll
            for (int j = 0; j < 10; ++j) {
                float2 Z = sZ[2 * qq][k0 + j];
                ger[j] = fmaf(Z.x, cs.x, fmaf(-Z.y, cs.y, ger[j]));
                gei[j] = fmaf(Z.x, cs.y, fmaf( Z.y, cs.x, gei[j]));
            }
            idx = (idx + step) & 255;
        }
        // odd q (f odd), f = -19, -17, ..., 19
        idx = (-19 * h) & 255;
        #pragma unroll 2
        for (int qq = 0; qq < 20; ++qq) {
            float2 cs = tw[idx];
            #pragma unroll
            for (int j = 0; j < 10; ++j) {
                float2 Z = sZ[2 * qq + 1][k0 + j];
                gor[j] = fmaf(Z.x, cs.x, fmaf(-Z.y, cs.y, gor[j]));
                goi[j] = fmaf(Z.x, cs.y, fmaf( Z.y, cs.x, goi[j]));
            }
            idx = (idx + step) & 255;
        }
        #pragma unroll
        for (int j = 0; j < 10; ++j) {
            int k = k0 + j;
            sGx[k][h]       = ger[j] + gor[j];
            sGx[k][h + 128] = ger[j] - gor[j];
            if (k > 0) {
                sGy[k - 1][h]       = gei[j] + goi[j];
                sGy[k - 1][h + 128] = gei[j] - goi[j];
            }
        }
    }
    __syncthreads();

    // ---- phase 2: 4h x 4w tiles, twiddles from smem tables ----
    int wg = tid & 31;        // wp0 = 4*wg
    int hgb = tid >> 5;       // 0..7
    int wp0 = wg * 4;
    const float sc = 2.0f / 65536.0f;

    #pragma unroll 1
    for (int it = 0; it < 8; ++it) {
        int h0 = it * 32 + hgb * 4;
        float C[4][4], S[4][4];
        {
            float4 g0 = *(const float4*)&sGx[0][h0];
            float g0a[4] = {g0.x, g0.y, g0.z, g0.w};
            #pragma unroll
            for (int a = 0; a < 4; ++a)
                #pragma unroll
                for (int b = 0; b < 4; ++b) { C[a][b] = 0.5f * g0a[a]; S[a][b] = 0.f; }
        }
        #pragma unroll
        for (int k = 1; k < M2; ++k) {
            float4 gx = *(const float4*)&sGx[k][h0];
            float4 gy = *(const float4*)&sGy[k - 1][h0];
            float4 cv = *(const float4*)&sC[k][wp0];
            float4 sv = *(const float4*)&sS[k][wp0];
            float gxa[4] = {gx.x, gx.y, gx.z, gx.w};
            float gya[4] = {gy.x, gy.y, gy.z, gy.w};
            float cva[4] = {cv.x, cv.y, cv.z, cv.w};
            float sva[4] = {sv.x, sv.y, sv.z, sv.w};
            #pragma unroll
            for (int a = 0; a < 4; ++a)
                #pragma unroll
                for (int b = 0; b < 4; ++b) {
                    C[a][b] = fmaf(gxa[a], cva[b], C[a][b]);
                    S[a][b] = fmaf(gya[a], sva[b], S[a][b]);
                }
        }

        size_t rowbase = ((size_t)bo * HH + h0) * WW;
        #pragma unroll
        for (int a = 0; a < 4; ++a) {
            float4 fo;
            fo.x = (C[a][0] - S[a][0]) * sc;
            fo.y = (C[a][1] - S[a][1]) * sc;
            fo.z = (C[a][2] - S[a][2]) * sc;
            fo.w = (C[a][3] - S[a][3]) * sc;
            *(float4*)&out[rowbase + (size_t)a * WW + wp0] = fo;
            #pragma unroll
            for (int b = 0; b < 4; ++b) {
                int wp = wp0 + b;
                if (wp) out[rowbase + (size_t)a * WW + (256 - wp)] = (C[a][b] + S[a][b]) * sc;
            }
        }
    }

    // ---- w = 128 column ----
    {
        int h = tid;
        float acc = 0.5f * sGx[0][h];
        #pragma unroll
        for (int k = 1; k < M2; ++k)
            acc += (k & 1) ? -sGx[k][h] : sGx[k][h];
        out[((size_t)bo * HH + h) * WW + 128] = acc * sc;
    }
}

extern "C" void kernel_launch(void* const* d_in, const int* in_sizes, int n_in,
                              void* d_out, int out_size) {
    const float* x   = (const float*)d_in[0];
    const float* w1r = (const float*)d_in[1];
    const float* w1i = (const float*)d_in[2];
    const float* w2r = (const float*)d_in[3];
    const float* w2i = (const float*)d_in[4];
    float* out = (float*)d_out;

    kA<<<(BB * CC * HH) / RA, 256>>>(x);       // 1024 blocks
    kB<<<BB * CC, 256>>>();                     // 1024 blocks
    kC<<<QQ * 5, 256>>>(w1r, w1i, w2r, w2i);    // 200 blocks
    kD<<<BB * CC, 256>>>(out);                  // 1024 blocks
}